// round 1
// baseline (speedup 1.0000x reference)
#include <cuda_runtime.h>
#include <math.h>

// ---------------------------------------------------------------------------
// YOLOv3 loss, B=32. Layers: 13x13 / 26x26 / 52x52, 3 anchors, 80 classes.
// y_true: (32, 3549, 3, 85) fp32 ; preds: (32,H,W,255) fp32 ; out: (32,) fp32
// ---------------------------------------------------------------------------

#define NB    32          // batch
#define TOT   10647       // cell-anchors per batch across all layers (507+2028+8112)
#define NBL   (NB*3)      // (batch, layer) pairs
#define STAGE 128         // staging capacity for positive boxes (expected <=~30)

__device__ int    g_cnt[NBL];
__device__ int    g_stage_idx[NBL][STAGE];
__device__ float4 g_stage_box[NBL][STAGE];
__device__ int    g_count_final[NBL];
__device__ float4 g_boxes[NBL][64];

__constant__ float c_anc[9][2] = {
    {116.f, 90.f}, {156.f, 198.f}, {373.f, 326.f},
    { 30.f, 61.f}, { 62.f,  45.f}, { 59.f, 119.f},
    { 10.f, 13.f}, { 16.f,  30.f}, { 33.f,  23.f}};

__device__ __forceinline__ float sigf(float x) { return 1.f / (1.f + __expf(-x)); }
__device__ __forceinline__ float bcef(float t, float x) {
    // max(x,0) - x*t + log1p(exp(-|x|))
    return fmaxf(x, 0.f) - x * t + log1pf(__expf(-fabsf(x)));
}

// ---- kernel 0: zero counters and output --------------------------------
__global__ void k_init(float* __restrict__ out) {
    int i = threadIdx.x;
    if (i < NBL) g_cnt[i] = 0;
    if (i < NB)  out[i] = 0.f;
}

// ---- kernel 1: collect positive (obj==1) boxes per (b,layer) -----------
__global__ void k_collect(const float* __restrict__ yt) {
    int e = blockIdx.x * blockDim.x + threadIdx.x;
    if (e >= NB * TOT) return;
    int b = e / TOT;
    int loc = e - b * TOT;
    int layer, cell_off;
    if (loc < 507)        { layer = 0; cell_off = 0; }
    else if (loc < 2535)  { layer = 1; cell_off = 169; loc -= 507; }
    else                  { layer = 2; cell_off = 845; loc -= 2535; }
    int cell = loc / 3, a = loc - cell * 3;
    const float* t = yt + (((size_t)b * 3549 + cell_off + cell) * 3 + a) * 85;
    if (t[0] > 0.5f) {
        int bl = b * 3 + layer;
        int slot = atomicAdd(&g_cnt[bl], 1);
        if (slot < STAGE) {
            g_stage_idx[bl][slot] = loc;  // within-layer flat index (order key)
            float4 bx;
            bx.x = t[1]; bx.y = t[2]; bx.z = t[3]; bx.w = t[4];
            g_stage_box[bl][slot] = bx;
        }
    }
}

// ---- kernel 2: finalize box lists (top-64 by lowest index, stable) ------
__global__ void k_select() {
    int bl = blockIdx.x;        // 0..95
    int lane = threadIdx.x;     // 32 threads
    int cnt = g_cnt[bl];
    if (cnt > STAGE) cnt = STAGE;
    if (cnt <= 64) {
        for (int k = lane; k < cnt; k += 32)
            g_boxes[bl][k] = g_stage_box[bl][k];
        if (lane == 0) g_count_final[bl] = cnt;
    } else {
        // >64 positives: keep the 64 smallest within-layer indices
        // (matches jax.lax.top_k stable tie-breaking on 0/1 values).
        for (int k = lane; k < cnt; k += 32) {
            int myidx = g_stage_idx[bl][k];
            int rank = 0;
            for (int m = 0; m < cnt; m++)
                rank += (g_stage_idx[bl][m] < myidx) ? 1 : 0;
            if (rank < 64) g_boxes[bl][rank] = g_stage_box[bl][k];
        }
        if (lane == 0) g_count_final[bl] = 64;
    }
}

// ---- kernel 3: main loss — one warp per cell-anchor ----------------------
#define WPB 8   // warps per block
__global__ __launch_bounds__(WPB * 32)
void k_main(const float* __restrict__ yt,
            const float* __restrict__ p13,
            const float* __restrict__ p26,
            const float* __restrict__ p52,
            float* __restrict__ out) {
    __shared__ float s_sum[WPB];
    __shared__ int   s_b[WPB];

    int wid  = threadIdx.x >> 5;
    int lane = threadIdx.x & 31;
    int warp = blockIdx.x * WPB + wid;

    float lsum = 0.f;
    int b = -1;

    if (warp < NB * TOT) {
        b = warp / TOT;
        int loc = warp - b * TOT;
        int layer, W, cell_off;
        if (loc < 507)       { layer = 0; W = 13; cell_off = 0; }
        else if (loc < 2535) { layer = 1; W = 26; cell_off = 169; loc -= 507; }
        else                 { layer = 2; W = 52; cell_off = 845; loc -= 2535; }
        int cell = loc / 3, a = loc - cell * 3;
        int hh = cell / W, ww = cell - hh * W;

        const float* pred = (layer == 0) ? p13 : (layer == 1) ? p26 : p52;
        const float* pb = pred + ((size_t)(b * (W * W) + cell) * 255 + a * 85);
        const float* tb = yt + (((size_t)b * 3549 + cell_off + cell) * 3 + a) * 85;

        // coalesced channel loads: lane handles channels lane, lane+32, lane+64
        float t0 = tb[lane],      q0 = pb[lane];
        float t1 = tb[lane + 32], q1 = pb[lane + 32];
        float t2 = 0.f, q2 = 0.f;
        if (lane < 21) { t2 = tb[lane + 64]; q2 = pb[lane + 64]; }

        const unsigned FULL = 0xffffffffu;
        float obj = __shfl_sync(FULL, t0, 0);
        float tw  = __shfl_sync(FULL, t0, 3);
        float th  = __shfl_sync(FULL, t0, 4);
        float px1 = __shfl_sync(FULL, q0, 1);
        float px2 = __shfl_sync(FULL, q0, 2);
        float px3 = __shfl_sync(FULL, q0, 3);
        float px4 = __shfl_sync(FULL, q0, 4);

        float fW = (float)W;  // grid is square: fwh = (W, W)
        float aw = c_anc[3 * layer + a][0];
        float ah = c_anc[3 * layer + a][1];

        // predicted box (normalized units per reference)
        float bx = (sigf(px1) + (float)ww) / fW;
        float by = (sigf(px2) + (float)hh) / fW;
        float bw = __expf(px3) * aw / fW;
        float bh = __expf(px4) * ah / fW;

        // best IoU against true boxes (lanes split the <=64 boxes)
        int bl = b * 3 + layer;
        int cnt = g_count_final[bl];
        float pminx = bx - bw * 0.5f, pmaxx = bx + bw * 0.5f;
        float pminy = by - bh * 0.5f, pmaxy = by + bh * 0.5f;
        float pa = bw * bh;
        float best = -INFINITY;
        for (int k = lane; k < cnt; k += 32) {
            float4 t4 = g_boxes[bl][k];
            float tminx = t4.x - t4.z * 0.5f, tmaxx = t4.x + t4.z * 0.5f;
            float tminy = t4.y - t4.w * 0.5f, tmaxy = t4.y + t4.w * 0.5f;
            float iw = fmaxf(fminf(pmaxx, tmaxx) - fmaxf(pminx, tminx), 0.f);
            float ih = fmaxf(fminf(pmaxy, tmaxy) - fmaxf(pminy, tminy), 0.f);
            float inter = iw * ih;
            float iou = inter / (pa + t4.z * t4.w - inter);
            best = fmaxf(best, iou);
        }
        #pragma unroll
        for (int o = 16; o; o >>= 1)
            best = fmaxf(best, __shfl_xor_sync(FULL, best, o));
        float ignore = (best < 0.5f) ? 1.f : 0.f;

        // conf loss (channel 0) — always active
        if (lane == 0) {
            float conf = sigf(q0);
            lsum += bcef(obj, conf) * (obj + (1.f - obj) * ignore);
        }

        // obj-gated terms (obj is exactly 0 or 1; warp-uniform branch)
        if (obj > 0.f) {
            float scale = 2.f - tw * th;
            if (lane == 1) {          // x
                float x = (sigf(q0) + (float)ww) / fW;
                float t = t0 * fW - (float)ww;
                lsum += scale * bcef(t, x);
            } else if (lane == 2) {   // y
                float x = (sigf(q0) + (float)hh) / fW;
                float t = t0 * fW - (float)hh;
                lsum += scale * bcef(t, x);
            } else if (lane == 3) {   // w
                float w_ = __expf(q0) * aw / fW;
                float t = logf(t0 * 416.f / aw);
                float d = t - w_;
                lsum += scale * 0.5f * d * d;
            } else if (lane == 4) {   // h
                float h_ = __expf(q0) * ah / fW;
                float t = logf(t0 * 416.f / ah);
                float d = t - h_;
                lsum += scale * 0.5f * d * d;
            } else if (lane >= 5) {   // cls channels 5..31
                lsum += bcef(t0, sigf(q0));
            }
            lsum += bcef(t1, sigf(q1));                    // cls channels 32..63
            if (lane < 21) lsum += bcef(t2, sigf(q2));     // cls channels 64..84
        }

        // warp sum
        #pragma unroll
        for (int o = 16; o; o >>= 1)
            lsum += __shfl_xor_sync(FULL, lsum, o);
    }

    if (lane == 0) { s_sum[wid] = lsum; s_b[wid] = b; }
    __syncthreads();

    if (threadIdx.x == 0) {
        // combine runs of identical b (at most 2 distinct b per block)
        float acc = 0.f;
        int cb = s_b[0];
        #pragma unroll
        for (int i = 0; i < WPB; i++) {
            if (s_b[i] != cb) {
                if (cb >= 0) atomicAdd(out + cb, acc);
                acc = 0.f; cb = s_b[i];
            }
            acc += s_sum[i];
        }
        if (cb >= 0) atomicAdd(out + cb, acc);
    }
}

// ---------------------------------------------------------------------------
extern "C" void kernel_launch(void* const* d_in, const int* in_sizes, int n_in,
                              void* d_out, int out_size) {
    const float* yt  = (const float*)d_in[0];
    const float* p13 = (const float*)d_in[1];
    const float* p26 = (const float*)d_in[2];
    const float* p52 = (const float*)d_in[3];
    float* out = (float*)d_out;

    k_init<<<1, 128>>>(out);

    int total = NB * TOT;
    k_collect<<<(total + 255) / 256, 256>>>(yt);

    k_select<<<NBL, 32>>>();

    int warps = NB * TOT;
    int blocks = (warps + WPB - 1) / WPB;
    k_main<<<blocks, WPB * 32>>>(yt, p13, p26, p52, out);
}

// round 2
// speedup vs baseline: 3.8903x; 3.8903x over previous
#include <cuda_runtime.h>
#include <math.h>

// ---------------------------------------------------------------------------
// YOLOv3 loss, B=32. Layers: 13x13 / 26x26 / 52x52, 3 anchors, 80 classes.
// y_true: (32, 3549, 3, 85) fp32 ; preds: (32,H,W,255) fp32 ; out: (32,) fp32
//
// Structure:
//   k_init    : zero counters + out
//   k_collect : thread/anchor, gather positive boxes (precompute min/max/area)
//   k_select  : cap membership at 64 (top-k semantics; trivially a copy here)
//   k_main    : thread/anchor, conf-BCE + ignore mask only (6 floats/anchor)
//   k_pos     : warp/positive, xy/wh/cls terms (rare path)
// ---------------------------------------------------------------------------

#define NB    32
#define TOT   10647            // 507 + 2028 + 8112
#define NBL   (NB*3)
#define STAGE 128

__device__ int    g_cnt[NBL];
__device__ int    g_stage_idx[NBL][STAGE];
__device__ float4 g_stageA[NBL][STAGE];     // (minx, miny, maxx, maxy)
__device__ float  g_stageArea[NBL][STAGE];
__device__ int    g_fcnt[NBL];
__device__ float4 g_fA[NBL][64];
__device__ float  g_fArea[NBL][64];

__constant__ float c_anc[9][2] = {
    {116.f, 90.f}, {156.f, 198.f}, {373.f, 326.f},
    { 30.f, 61.f}, { 62.f,  45.f}, { 59.f, 119.f},
    { 10.f, 13.f}, { 16.f,  30.f}, { 33.f,  23.f}};

__device__ __forceinline__ float sigf(float x) {
    return __fdividef(1.f, 1.f + __expf(-x));
}
// bce_logits(t, x) for x in (0,1): max(x,0)=x, |x|=x
__device__ __forceinline__ float bce01(float t, float x) {
    return x - x * t + __logf(1.f + __expf(-x));
}

// ---- k_init --------------------------------------------------------------
__global__ void k_init(float* __restrict__ out) {
    int i = threadIdx.x;
    if (i < NBL) g_cnt[i] = 0;
    if (i < NB)  out[i] = 0.f;
}

// ---- k_collect -------------------------------------------------------------
__global__ void k_collect(const float* __restrict__ yt) {
    int e = blockIdx.x * blockDim.x + threadIdx.x;
    if (e >= NB * TOT) return;
    int b = e / TOT;
    int loc = e - b * TOT;
    int layer, cell_off, l = loc;
    if (l < 507)        { layer = 0; cell_off = 0; }
    else if (l < 2535)  { layer = 1; cell_off = 169; l -= 507; }
    else                { layer = 2; cell_off = 845; l -= 2535; }
    int cell = l / 3, a = l - cell * 3;
    const float* t = yt + (((size_t)b * 3549 + cell_off + cell) * 3 + a) * 85;
    if (t[0] > 0.5f) {
        float t1 = t[1], t2 = t[2], t3 = t[3], t4 = t[4];
        int bl = b * 3 + layer;
        int slot = atomicAdd(&g_cnt[bl], 1);
        if (slot < STAGE) {
            g_stage_idx[bl][slot] = l;
            g_stageA[bl][slot] = make_float4(t1 - 0.5f * t3, t2 - 0.5f * t4,
                                             t1 + 0.5f * t3, t2 + 0.5f * t4);
            g_stageArea[bl][slot] = t3 * t4;
        }
    }
}

// ---- k_select --------------------------------------------------------------
__global__ void k_select() {
    int bl = blockIdx.x, lane = threadIdx.x;
    int cnt = g_cnt[bl];
    if (cnt > STAGE) cnt = STAGE;
    if (cnt <= 64) {
        for (int k = lane; k < cnt; k += 32) {
            g_fA[bl][k] = g_stageA[bl][k];
            g_fArea[bl][k] = g_stageArea[bl][k];
        }
        if (lane == 0) g_fcnt[bl] = cnt;
    } else {
        // keep 64 smallest within-layer indices (stable top-k on 0/1 values)
        for (int k = lane; k < cnt; k += 32) {
            int myidx = g_stage_idx[bl][k];
            int rank = 0;
            for (int m = 0; m < cnt; m++)
                rank += (g_stage_idx[bl][m] < myidx) ? 1 : 0;
            if (rank < 64) {
                g_fA[bl][rank] = g_stageA[bl][k];
                g_fArea[bl][rank] = g_stageArea[bl][k];
            }
        }
        if (lane == 0) g_fcnt[bl] = 64;
    }
}

// ---- k_main ----------------------------------------------------------------
template<int W, int LAYER, int CELL_OFF>
__device__ __forceinline__ float main_work(
    int b, int chunk, const float* __restrict__ yt,
    const float* __restrict__ pred,
    const float4* sA, const float* sArea, int cnt)
{
    constexpr int NANCH = W * W * 3;
    int loc = chunk * 256 + threadIdx.x;
    if (loc >= NANCH) return 0.f;

    int cell = loc / 3, a = loc - cell * 3;
    int hh = cell / W, ww = cell - hh * W;
    const float* pb = pred + ((size_t)(b * (W * W) + cell)) * 255 + a * 85;
    const float* tb = yt + (((size_t)b * 3549 + CELL_OFF + cell) * 3 + a) * 85;

    float obj = tb[0];
    float q0  = pb[0];

    float ignore = 1.f;
    if (cnt > 0) {
        float q1 = pb[1], q2 = pb[2], q3 = pb[3], q4 = pb[4];
        constexpr float invW = 1.f / (float)W;
        float aw = c_anc[3 * LAYER + a][0];
        float ah = c_anc[3 * LAYER + a][1];
        float bx = (sigf(q1) + (float)ww) * invW;
        float by = (sigf(q2) + (float)hh) * invW;
        float bw = __expf(q3) * (aw * invW);
        float bh = __expf(q4) * (ah * invW);
        float hx = 0.5f * bw, hy = 0.5f * bh;
        float pminx = bx - hx, pmaxx = bx + hx;
        float pminy = by - hy, pmaxy = by + hy;
        float pa = bw * bh;
        bool hit = false;
        for (int k = 0; k < cnt; k++) {
            float4 A = sA[k];
            float iw = fminf(pmaxx, A.z) - fmaxf(pminx, A.x);
            float ih = fminf(pmaxy, A.w) - fmaxf(pminy, A.y);
            iw = fmaxf(iw, 0.f); ih = fmaxf(ih, 0.f);
            float inter = iw * ih;
            // iou >= 0.5  <=>  3*inter >= pa + ta
            hit = hit || (3.f * inter >= pa + sArea[k]);
        }
        if (hit) ignore = 0.f;
    }

    float conf = sigf(q0);
    float bce  = bce01(obj, conf);
    float f    = (obj > 0.f) ? 1.f : ignore;
    return bce * f;
}

__global__ __launch_bounds__(256)
void k_main(const float* __restrict__ yt,
            const float* __restrict__ p13,
            const float* __restrict__ p26,
            const float* __restrict__ p52,
            float* __restrict__ out) {
    __shared__ float4 sA[64];
    __shared__ float  sArea[64];
    __shared__ float  sred[8];

    int bx = blockIdx.x;
    int b = bx / 42, r = bx - b * 42;
    int layer = (r < 2) ? 0 : (r < 10) ? 1 : 2;
    int bl = b * 3 + layer;
    int cnt = g_fcnt[bl];
    if (threadIdx.x < cnt) {
        sA[threadIdx.x] = g_fA[bl][threadIdx.x];
        sArea[threadIdx.x] = g_fArea[bl][threadIdx.x];
    }
    __syncthreads();

    float lsum;
    if (r < 2)       lsum = main_work<13, 0, 0>  (b, r,      yt, p13, sA, sArea, cnt);
    else if (r < 10) lsum = main_work<26, 1, 169>(b, r - 2,  yt, p26, sA, sArea, cnt);
    else             lsum = main_work<52, 2, 845>(b, r - 10, yt, p52, sA, sArea, cnt);

    // block reduce -> one atomic
    const unsigned FULL = 0xffffffffu;
    #pragma unroll
    for (int o = 16; o; o >>= 1) lsum += __shfl_xor_sync(FULL, lsum, o);
    int wid = threadIdx.x >> 5, lane = threadIdx.x & 31;
    if (lane == 0) sred[wid] = lsum;
    __syncthreads();
    if (wid == 0) {
        float v = (lane < 8) ? sred[lane] : 0.f;
        #pragma unroll
        for (int o = 4; o; o >>= 1) v += __shfl_xor_sync(FULL, v, o);
        if (lane == 0) atomicAdd(out + b, v);
    }
}

// ---- k_pos: xy/wh/cls terms for positives ----------------------------------
__global__ void k_pos(const float* __restrict__ yt,
                      const float* __restrict__ p13,
                      const float* __restrict__ p26,
                      const float* __restrict__ p52,
                      float* __restrict__ out) {
    int bl = blockIdx.x;
    int b = bl / 3, layer = bl - b * 3;
    int cnt = g_cnt[bl];
    if (cnt > STAGE) cnt = STAGE;
    if (cnt == 0) return;

    int wid = threadIdx.x >> 5, lane = threadIdx.x & 31;
    int W, cell_off;
    const float* pred;
    if (layer == 0)      { W = 13; cell_off = 0;   pred = p13; }
    else if (layer == 1) { W = 26; cell_off = 169; pred = p26; }
    else                 { W = 52; cell_off = 845; pred = p52; }
    float fW = (float)W, invW = 1.f / fW;
    const unsigned FULL = 0xffffffffu;

    float acc = 0.f;
    for (int k = wid; k < cnt; k += 2) {
        int loc = g_stage_idx[bl][k];
        int cell = loc / 3, a = loc - cell * 3;
        int hh = cell / W, ww = cell - hh * W;
        const float* pb = pred + ((size_t)(b * (W * W) + cell)) * 255 + a * 85;
        const float* tb = yt + (((size_t)b * 3549 + cell_off + cell) * 3 + a) * 85;
        float aw = c_anc[3 * layer + a][0];
        float ah = c_anc[3 * layer + a][1];

        // group 0: channels 1..32
        float t0 = tb[lane + 1], q0 = pb[lane + 1];
        float tw = __shfl_sync(FULL, t0, 2);   // yt ch3
        float th = __shfl_sync(FULL, t0, 3);   // yt ch4
        float scale = 2.f - tw * th;
        float l = 0.f;
        if (lane == 0) {          // x
            float x = (sigf(q0) + (float)ww) * invW;
            float t = t0 * fW - (float)ww;
            l = scale * bce01(t, x);
        } else if (lane == 1) {   // y
            float x = (sigf(q0) + (float)hh) * invW;
            float t = t0 * fW - (float)hh;
            l = scale * bce01(t, x);
        } else if (lane == 2) {   // w
            float wp = __expf(q0) * aw * invW;
            float t = __logf(t0 * (416.f / aw));
            float d = t - wp;
            l = scale * 0.5f * d * d;
        } else if (lane == 3) {   // h
            float hp = __expf(q0) * ah * invW;
            float t = __logf(t0 * (416.f / ah));
            float d = t - hp;
            l = scale * 0.5f * d * d;
        } else {                  // cls channels 5..32
            l = bce01(t0, sigf(q0));
        }
        // group 1: channels 33..64 (all cls)
        float t1 = tb[lane + 33], q1 = pb[lane + 33];
        l += bce01(t1, sigf(q1));
        // group 2: channels 65..84 (cls)
        if (lane < 20) {
            float t2 = tb[lane + 65], q2 = pb[lane + 65];
            l += bce01(t2, sigf(q2));
        }
        acc += l;
    }
    #pragma unroll
    for (int o = 16; o; o >>= 1) acc += __shfl_xor_sync(FULL, acc, o);
    if (lane == 0 && acc != 0.f) atomicAdd(out + b, acc);
}

// ---------------------------------------------------------------------------
extern "C" void kernel_launch(void* const* d_in, const int* in_sizes, int n_in,
                              void* d_out, int out_size) {
    const float* yt  = (const float*)d_in[0];
    const float* p13 = (const float*)d_in[1];
    const float* p26 = (const float*)d_in[2];
    const float* p52 = (const float*)d_in[3];
    float* out = (float*)d_out;

    k_init<<<1, 128>>>(out);
    k_collect<<<(NB * TOT + 255) / 256, 256>>>(yt);
    k_select<<<NBL, 32>>>();
    k_main<<<NB * 42, 256>>>(yt, p13, p26, p52, out);
    k_pos<<<NBL, 64>>>(yt, p13, p26, p52, out);
}

// round 3
// speedup vs baseline: 4.1144x; 1.0576x over previous
#include <cuda_runtime.h>
#include <math.h>

// ---------------------------------------------------------------------------
// YOLOv3 loss, B=32. Layers: 13x13 / 26x26 / 52x52, 3 anchors, 80 classes.
// y_true: (32, 3549, 3, 85) fp32 ; preds: (32,H,W,255) fp32 ; out: (32,) fp32
//
//   k_init    : zero counters + out
//   k_collect : thread/anchor, gather positive boxes + obj bitmask (ballot)
//   k_selpos  : per (b,layer): cap boxes at 64 (top-k) AND positive-term loss
//   k_main    : thread/anchor, conf-BCE + ignore mask; reads pred + bitmask only
// ---------------------------------------------------------------------------

#define NB    32
#define TOT   10647            // 507 + 2028 + 8112
#define NBL   (NB*3)
#define STAGE 128
#define NWORDS ((NB*TOT + 31) / 32 + 1)

__device__ int          g_cnt[NBL];
__device__ int          g_stage_idx[NBL][STAGE];
__device__ float4       g_stageA[NBL][STAGE];     // (minx, miny, maxx, maxy)
__device__ float        g_stageArea[NBL][STAGE];
__device__ int          g_fcnt[NBL];
__device__ float4       g_fA[NBL][64];
__device__ float        g_fArea[NBL][64];
__device__ unsigned int g_mask[NWORDS];

__constant__ float c_anc[9][2] = {
    {116.f, 90.f}, {156.f, 198.f}, {373.f, 326.f},
    { 30.f, 61.f}, { 62.f,  45.f}, { 59.f, 119.f},
    { 10.f, 13.f}, { 16.f,  30.f}, { 33.f,  23.f}};

__device__ __forceinline__ float sigf(float x) {
    return __fdividef(1.f, 1.f + __expf(-x));
}
// bce_logits(t, x) for x in (0,1): max(x,0)=x, |x|=x
__device__ __forceinline__ float bce01(float t, float x) {
    return x - x * t + __logf(1.f + __expf(-x));
}

// ---- k_init ---------------------------------------------------------------
__global__ void k_init(float* __restrict__ out) {
    int i = threadIdx.x;
    if (i < NBL) g_cnt[i] = 0;
    if (i < NB)  out[i] = 0.f;
}

// ---- k_collect --------------------------------------------------------------
__global__ __launch_bounds__(256)
void k_collect(const float* __restrict__ yt) {
    int e = blockIdx.x * blockDim.x + threadIdx.x;
    const unsigned FULL = 0xffffffffu;
    bool pos = false;
    int b = 0, l = 0, layer = 0, cell_off = 0;
    const float* t = yt;
    if (e < NB * TOT) {
        b = e / TOT;
        l = e - b * TOT;
        if (l < 507)        { layer = 0; cell_off = 0; }
        else if (l < 2535)  { layer = 1; cell_off = 169; l -= 507; }
        else                { layer = 2; cell_off = 845; l -= 2535; }
        int cell = l / 3, a = l - cell * 3;
        t = yt + (((size_t)b * 3549 + cell_off + cell) * 3 + a) * 85;
        pos = (t[0] > 0.5f);
    }
    unsigned m = __ballot_sync(FULL, pos);
    if ((threadIdx.x & 31) == 0) g_mask[e >> 5] = m;
    if (pos) {
        float t1 = t[1], t2 = t[2], t3 = t[3], t4 = t[4];
        int bl = b * 3 + layer;
        int slot = atomicAdd(&g_cnt[bl], 1);
        if (slot < STAGE) {
            g_stage_idx[bl][slot] = l;
            g_stageA[bl][slot] = make_float4(t1 - 0.5f * t3, t2 - 0.5f * t4,
                                             t1 + 0.5f * t3, t2 + 0.5f * t4);
            g_stageArea[bl][slot] = t3 * t4;
        }
    }
}

// ---- k_selpos: select top-64 boxes AND compute positive-anchor loss ---------
__global__ __launch_bounds__(64)
void k_selpos(const float* __restrict__ yt,
              const float* __restrict__ p13,
              const float* __restrict__ p26,
              const float* __restrict__ p52,
              float* __restrict__ out) {
    int bl = blockIdx.x;
    int b = bl / 3, layer = bl - b * 3;
    int wid = threadIdx.x >> 5, lane = threadIdx.x & 31;
    const unsigned FULL = 0xffffffffu;

    int cnt = g_cnt[bl];
    if (cnt > STAGE) cnt = STAGE;

    // --- selection (warp 0 only; expected path is a plain copy) ---
    if (wid == 0) {
        if (cnt <= 64) {
            for (int k = lane; k < cnt; k += 32) {
                g_fA[bl][k] = g_stageA[bl][k];
                g_fArea[bl][k] = g_stageArea[bl][k];
            }
            if (lane == 0) g_fcnt[bl] = cnt;
        } else {
            // keep 64 smallest within-layer indices (stable top-k on 0/1 vals)
            for (int k = lane; k < cnt; k += 32) {
                int myidx = g_stage_idx[bl][k];
                int rank = 0;
                for (int m = 0; m < cnt; m++)
                    rank += (g_stage_idx[bl][m] < myidx) ? 1 : 0;
                if (rank < 64) {
                    g_fA[bl][rank] = g_stageA[bl][k];
                    g_fArea[bl][rank] = g_stageArea[bl][k];
                }
            }
            if (lane == 0) g_fcnt[bl] = 64;
        }
    }

    // --- positive terms (both warps, warp per positive) ---
    if (cnt == 0) return;
    int W, cell_off;
    const float* pred;
    if (layer == 0)      { W = 13; cell_off = 0;   pred = p13; }
    else if (layer == 1) { W = 26; cell_off = 169; pred = p26; }
    else                 { W = 52; cell_off = 845; pred = p52; }
    float fW = (float)W, invW = 1.f / fW;

    float acc = 0.f;
    for (int k = wid; k < cnt; k += 2) {
        int loc = g_stage_idx[bl][k];
        int cell = loc / 3, a = loc - cell * 3;
        int hh = cell / W, ww = cell - hh * W;
        const float* pb = pred + ((size_t)(b * (W * W) + cell)) * 255 + a * 85;
        const float* tb = yt + (((size_t)b * 3549 + cell_off + cell) * 3 + a) * 85;
        float aw = c_anc[3 * layer + a][0];
        float ah = c_anc[3 * layer + a][1];

        // group 0: channels 1..32
        float t0 = tb[lane + 1], q0 = pb[lane + 1];
        float tw = __shfl_sync(FULL, t0, 2);   // yt ch3
        float th = __shfl_sync(FULL, t0, 3);   // yt ch4
        float scale = 2.f - tw * th;
        float l = 0.f;
        if (lane == 0) {          // x
            float x = (sigf(q0) + (float)ww) * invW;
            float t = t0 * fW - (float)ww;
            l = scale * bce01(t, x);
        } else if (lane == 1) {   // y
            float x = (sigf(q0) + (float)hh) * invW;
            float t = t0 * fW - (float)hh;
            l = scale * bce01(t, x);
        } else if (lane == 2) {   // w
            float wp = __expf(q0) * aw * invW;
            float t = __logf(t0 * (416.f / aw));
            float d = t - wp;
            l = scale * 0.5f * d * d;
        } else if (lane == 3) {   // h
            float hp = __expf(q0) * ah * invW;
            float t = __logf(t0 * (416.f / ah));
            float d = t - hp;
            l = scale * 0.5f * d * d;
        } else {                  // cls channels 5..32
            l = bce01(t0, sigf(q0));
        }
        // group 1: channels 33..64 (all cls)
        float t1 = tb[lane + 33], q1 = pb[lane + 33];
        l += bce01(t1, sigf(q1));
        // group 2: channels 65..84 (cls)
        if (lane < 20) {
            float t2 = tb[lane + 65], q2 = pb[lane + 65];
            l += bce01(t2, sigf(q2));
        }
        acc += l;
    }
    #pragma unroll
    for (int o = 16; o; o >>= 1) acc += __shfl_xor_sync(FULL, acc, o);
    if (lane == 0 && acc != 0.f) atomicAdd(out + b, acc);
}

// ---- k_main -----------------------------------------------------------------
template<int W, int LAYER, int ABASE>
__device__ __forceinline__ float main_work(
    int b, int chunk, const float* __restrict__ pred,
    const float4* sA, const float* sArea, int cnt)
{
    constexpr int NANCH = W * W * 3;
    int loc = chunk * 256 + threadIdx.x;
    if (loc >= NANCH) return 0.f;

    int cell = loc / 3, a = loc - cell * 3;
    int hh = cell / W, ww = cell - hh * W;
    const float* pb = pred + ((size_t)(b * (W * W) + cell)) * 255 + a * 85;

    // obj from bitmask (exact 0/1)
    int bit = b * TOT + ABASE + loc;
    unsigned mw = g_mask[bit >> 5];
    float obj = (float)((mw >> (bit & 31)) & 1u);

    float q0 = pb[0];

    float ignore = 1.f;
    if (cnt > 0) {
        float q1 = pb[1], q2 = pb[2], q3 = pb[3], q4 = pb[4];
        constexpr float invW = 1.f / (float)W;
        float aw = c_anc[3 * LAYER + a][0];
        float ah = c_anc[3 * LAYER + a][1];
        float bx = (sigf(q1) + (float)ww) * invW;
        float by = (sigf(q2) + (float)hh) * invW;
        float bw = __expf(q3) * (aw * invW);
        float bh = __expf(q4) * (ah * invW);
        float hx = 0.5f * bw, hy = 0.5f * bh;
        float pminx = bx - hx, pmaxx = bx + hx;
        float pminy = by - hy, pmaxy = by + hy;
        float pa = bw * bh;
        bool hit = false;
        for (int k = 0; k < cnt; k++) {
            float4 A = sA[k];
            float iw = fminf(pmaxx, A.z) - fmaxf(pminx, A.x);
            float ih = fminf(pmaxy, A.w) - fmaxf(pminy, A.y);
            iw = fmaxf(iw, 0.f); ih = fmaxf(ih, 0.f);
            float inter = iw * ih;
            // iou >= 0.5  <=>  3*inter >= pa + ta
            hit = hit || (3.f * inter >= pa + sArea[k]);
        }
        if (hit) ignore = 0.f;
    }

    float conf = sigf(q0);
    float bce  = bce01(obj, conf);
    float f    = (obj > 0.f) ? 1.f : ignore;
    return bce * f;
}

__global__ __launch_bounds__(256)
void k_main(const float* __restrict__ p13,
            const float* __restrict__ p26,
            const float* __restrict__ p52,
            float* __restrict__ out) {
    __shared__ float4 sA[64];
    __shared__ float  sArea[64];
    __shared__ float  sred[8];

    int bx = blockIdx.x;
    int b = bx / 42, r = bx - b * 42;
    int layer = (r < 2) ? 0 : (r < 10) ? 1 : 2;
    int bl = b * 3 + layer;
    int cnt = g_fcnt[bl];
    if (threadIdx.x < cnt) {
        sA[threadIdx.x] = g_fA[bl][threadIdx.x];
        sArea[threadIdx.x] = g_fArea[bl][threadIdx.x];
    }
    __syncthreads();

    float lsum;
    if (r < 2)       lsum = main_work<13, 0, 0>   (b, r,      p13, sA, sArea, cnt);
    else if (r < 10) lsum = main_work<26, 1, 507> (b, r - 2,  p26, sA, sArea, cnt);
    else             lsum = main_work<52, 2, 2535>(b, r - 10, p52, sA, sArea, cnt);

    // block reduce -> one atomic
    const unsigned FULL = 0xffffffffu;
    #pragma unroll
    for (int o = 16; o; o >>= 1) lsum += __shfl_xor_sync(FULL, lsum, o);
    int wid = threadIdx.x >> 5, lane = threadIdx.x & 31;
    if (lane == 0) sred[wid] = lsum;
    __syncthreads();
    if (wid == 0) {
        float v = (lane < 8) ? sred[lane] : 0.f;
        #pragma unroll
        for (int o = 4; o; o >>= 1) v += __shfl_xor_sync(FULL, v, o);
        if (lane == 0) atomicAdd(out + b, v);
    }
}

// ---------------------------------------------------------------------------
extern "C" void kernel_launch(void* const* d_in, const int* in_sizes, int n_in,
                              void* d_out, int out_size) {
    const float* yt  = (const float*)d_in[0];
    const float* p13 = (const float*)d_in[1];
    const float* p26 = (const float*)d_in[2];
    const float* p52 = (const float*)d_in[3];
    float* out = (float*)d_out;

    k_init<<<1, 128>>>(out);
    k_collect<<<(NB * TOT + 255) / 256, 256>>>(yt);
    k_selpos<<<NBL, 64>>>(yt, p13, p26, p52, out);
    k_main<<<NB * 42, 256>>>(p13, p26, p52, out);
}

// round 4
// speedup vs baseline: 7.0403x; 1.7111x over previous
#include <cuda_runtime.h>
#include <math.h>

// ---------------------------------------------------------------------------
// YOLOv3 loss, B=32. Layers: 13x13 / 26x26 / 52x52, 3 anchors, 80 classes.
// y_true: (32, 3549, 3, 85) fp32 ; preds: (32,H,W,255) fp32 ; out: (32,) fp32
//
//   k_init    : zero counters + out (tiny)
//   k_collect : 2 anchors/thread; obj bitmask via ballot; stage positive boxes
//   k_main    : blocks [0,96)  -> positive-anchor xy/wh/cls loss (warp/positive)
//               blocks [96,..) -> 512 anchors/block, conf-BCE + ignore mask
// ---------------------------------------------------------------------------

#define NB     32
#define TOT    10647            // 507 + 2028 + 8112
#define NTOT   (NB*TOT)         // 340704
#define NBL    96
#define STAGE  128
#define NPOS   96
#define NMAIN  666              // ceil(340704/512)
#define NWORDS 10656

__device__ int      g_cnt[NBL];
__device__ int      g_stage_idx[NBL][STAGE];
__device__ float4   g_stageA[NBL][STAGE];     // (minx, miny, maxx, maxy)
__device__ float    g_stageArea[NBL][STAGE];
__device__ unsigned g_mask[NWORDS];

__constant__ float c_anc[9][2] = {
    {116.f, 90.f}, {156.f, 198.f}, {373.f, 326.f},
    { 30.f, 61.f}, { 62.f,  45.f}, { 59.f, 119.f},
    { 10.f, 13.f}, { 16.f,  30.f}, { 33.f,  23.f}};

__device__ __forceinline__ float sigf(float x) {
    return __fdividef(1.f, 1.f + __expf(-x));
}
// bce_logits(t, x) for x in (0,1): max(x,0)=x, |x|=x
__device__ __forceinline__ float bce01(float t, float x) {
    return x - x * t + __logf(1.f + __expf(-x));
}

// decode global anchor e -> (b, layer, loc-within-layer)
__device__ __forceinline__ void decode(int e, int& b, int& layer, int& l,
                                       int& cell_off) {
    b = e / TOT;
    l = e - b * TOT;
    if (l < 507)        { layer = 0; cell_off = 0; }
    else if (l < 2535)  { layer = 1; cell_off = 169; l -= 507; }
    else                { layer = 2; cell_off = 845; l -= 2535; }
}

// ---- k_init -----------------------------------------------------------------
__global__ void k_init(float* __restrict__ out) {
    int i = threadIdx.x;
    if (i < NBL) g_cnt[i] = 0;
    if (i < NB)  out[i] = 0.f;
}

// ---- k_collect ----------------------------------------------------------------
__device__ __forceinline__ bool collect_probe(int e, const float* __restrict__ yt,
                                              const float*& t, int& bl, int& l) {
    if (e >= NTOT) return false;
    int b, layer, cell_off;
    decode(e, b, layer, l, cell_off);
    int cell = l / 3, a = l - cell * 3;
    t = yt + (((size_t)b * 3549 + cell_off + cell) * 3 + a) * 85;
    bl = b * 3 + layer;
    return __ldg(t) > 0.5f;
}
__device__ __forceinline__ void collect_stage(const float* t, int bl, int l) {
    float t1 = __ldg(t + 1), t2 = __ldg(t + 2), t3 = __ldg(t + 3), t4 = __ldg(t + 4);
    int slot = atomicAdd(&g_cnt[bl], 1);
    if (slot < STAGE) {
        g_stage_idx[bl][slot] = l;
        g_stageA[bl][slot] = make_float4(t1 - 0.5f * t3, t2 - 0.5f * t4,
                                         t1 + 0.5f * t3, t2 + 0.5f * t4);
        g_stageArea[bl][slot] = t3 * t4;
    }
}

__global__ __launch_bounds__(256)
void k_collect(const float* __restrict__ yt) {
    const unsigned FULL = 0xffffffffu;
    int gw = blockIdx.x * 8 + (threadIdx.x >> 5);   // global warp
    int lane = threadIdx.x & 31;
    int base = gw * 64;
    int e0 = base + lane, e1 = base + 32 + lane;

    const float *tp0 = nullptr, *tp1 = nullptr;
    int bl0 = 0, l0 = 0, bl1 = 0, l1 = 0;
    bool p0 = collect_probe(e0, yt, tp0, bl0, l0);
    bool p1 = collect_probe(e1, yt, tp1, bl1, l1);

    unsigned m0 = __ballot_sync(FULL, p0);
    unsigned m1 = __ballot_sync(FULL, p1);
    if (lane == 0) {
        g_mask[base >> 5] = m0;
        g_mask[(base >> 5) + 1] = m1;
    }
    if (p0) collect_stage(tp0, bl0, l0);
    if (p1) collect_stage(tp1, bl1, l1);
}

// ---- k_main: anchor work ------------------------------------------------------
struct AnchGeom {
    float pminx, pminy, pmaxx, pmaxy, pa;
    float confbce;     // bce(obj, conf)
    float obj;
    int bl;
    bool valid;
};

__device__ __forceinline__ AnchGeom anchor_setup(
    int e, const float* __restrict__ p13, const float* __restrict__ p26,
    const float* __restrict__ p52) {
    AnchGeom g;
    g.valid = (e < NTOT);
    if (!g.valid) { g.bl = -1; g.confbce = 0.f; g.obj = 0.f; return g; }
    int b, layer, l, cell_off;
    decode(e, b, layer, l, cell_off);
    g.bl = b * 3 + layer;
    int cell = l / 3, a = l - cell * 3;
    int W = (layer == 0) ? 13 : (layer == 1) ? 26 : 52;
    int hh = cell / W, ww = cell - hh * W;
    const float* pred = (layer == 0) ? p13 : (layer == 1) ? p26 : p52;
    const float* pb = pred + ((size_t)(b * (W * W) + cell)) * 255 + a * 85;

    unsigned mw = g_mask[e >> 5];
    g.obj = (float)((mw >> (e & 31)) & 1u);

    float q0 = __ldg(pb);
    float q1 = __ldg(pb + 1), q2 = __ldg(pb + 2);
    float q3 = __ldg(pb + 3), q4 = __ldg(pb + 4);

    float invW = __fdividef(1.f, (float)W);
    float aw = c_anc[3 * layer + a][0];
    float ah = c_anc[3 * layer + a][1];
    float bx = (sigf(q1) + (float)ww) * invW;
    float by = (sigf(q2) + (float)hh) * invW;
    float bw = __expf(q3) * (aw * invW);
    float bh = __expf(q4) * (ah * invW);
    float hx = 0.5f * bw, hy = 0.5f * bh;
    g.pminx = bx - hx; g.pmaxx = bx + hx;
    g.pminy = by - hy; g.pmaxy = by + hy;
    g.pa = bw * bh;
    g.confbce = bce01(g.obj, sigf(q0));
    return g;
}

__device__ __forceinline__ bool box_hit(const AnchGeom& g, float4 A, float ta) {
    float iw = fminf(g.pmaxx, A.z) - fmaxf(g.pminx, A.x);
    float ih = fminf(g.pmaxy, A.w) - fmaxf(g.pminy, A.y);
    iw = fmaxf(iw, 0.f); ih = fmaxf(ih, 0.f);
    float inter = iw * ih;
    return 3.f * inter >= g.pa + ta;        // iou >= 0.5
}

// loop over staged boxes of bl; returns ignore flag (1 = no overlap >= 0.5)
__device__ __forceinline__ void box_scan(const AnchGeom& gA, const AnchGeom& gB,
                                         bool same_bl, float& ignA, float& ignB) {
    ignA = 1.f; ignB = 1.f;
    if (same_bl && gA.valid) {
        int cnt = g_cnt[gA.bl];
        int use = min(cnt, STAGE);
        bool rare = use > 64;
        bool hA = false, hB = false;
        for (int k = 0; k < use; k++) {
            if (rare) {  // top-64 by smallest within-layer index (never in practice)
                int idx = g_stage_idx[gA.bl][k];
                int rank = 0;
                for (int m = 0; m < use; m++)
                    rank += (g_stage_idx[gA.bl][m] < idx) ? 1 : 0;
                if (rank >= 64) continue;
            }
            float4 A = g_stageA[gA.bl][k];
            float ta = g_stageArea[gA.bl][k];
            hA = hA || box_hit(gA, A, ta);
            hB = hB || box_hit(gB, A, ta);
        }
        if (hA) ignA = 0.f;
        if (hB) ignB = 0.f;
    } else {
        const AnchGeom* gs[2] = {&gA, &gB};
        float* igs[2] = {&ignA, &ignB};
        for (int s = 0; s < 2; s++) {
            const AnchGeom& g = *gs[s];
            if (!g.valid) continue;
            int use = min(g_cnt[g.bl], STAGE);
            bool rare = use > 64;
            bool h = false;
            for (int k = 0; k < use; k++) {
                if (rare) {
                    int idx = g_stage_idx[g.bl][k];
                    int rank = 0;
                    for (int m = 0; m < use; m++)
                        rank += (g_stage_idx[g.bl][m] < idx) ? 1 : 0;
                    if (rank >= 64) continue;
                }
                h = h || box_hit(g, g_stageA[g.bl][k], g_stageArea[g.bl][k]);
            }
            if (h) *igs[s] = 0.f;
        }
    }
}

// ---- positive-anchor loss (blocks [0, 96)) -----------------------------------
__device__ void pos_work(int bl, const float* __restrict__ yt,
                         const float* __restrict__ p13,
                         const float* __restrict__ p26,
                         const float* __restrict__ p52,
                         float* __restrict__ out) {
    int b = bl / 3, layer = bl - b * 3;
    int cnt = g_cnt[bl];
    if (cnt > STAGE) cnt = STAGE;
    if (cnt == 0) return;

    int wid = threadIdx.x >> 5, lane = threadIdx.x & 31;
    const unsigned FULL = 0xffffffffu;
    int W, cell_off;
    const float* pred;
    if (layer == 0)      { W = 13; cell_off = 0;   pred = p13; }
    else if (layer == 1) { W = 26; cell_off = 169; pred = p26; }
    else                 { W = 52; cell_off = 845; pred = p52; }
    float fW = (float)W, invW = __fdividef(1.f, fW);

    float acc = 0.f;
    for (int k = wid; k < cnt; k += 8) {
        int loc = g_stage_idx[bl][k];
        int cell = loc / 3, a = loc - cell * 3;
        int hh = cell / W, ww = cell - hh * W;
        const float* pb = pred + ((size_t)(b * (W * W) + cell)) * 255 + a * 85;
        const float* tb = yt + (((size_t)b * 3549 + cell_off + cell) * 3 + a) * 85;
        float aw = c_anc[3 * layer + a][0];
        float ah = c_anc[3 * layer + a][1];

        // group 0: channels 1..32
        float t0 = __ldg(tb + lane + 1), q0 = __ldg(pb + lane + 1);
        float tw = __shfl_sync(FULL, t0, 2);   // yt ch3
        float th = __shfl_sync(FULL, t0, 3);   // yt ch4
        float scale = 2.f - tw * th;
        float l = 0.f;
        if (lane == 0) {          // x
            float x = (sigf(q0) + (float)ww) * invW;
            float t = t0 * fW - (float)ww;
            l = scale * bce01(t, x);
        } else if (lane == 1) {   // y
            float x = (sigf(q0) + (float)hh) * invW;
            float t = t0 * fW - (float)hh;
            l = scale * bce01(t, x);
        } else if (lane == 2) {   // w
            float wp = __expf(q0) * aw * invW;
            float t = __logf(t0 * (416.f / aw));
            float d = t - wp;
            l = scale * 0.5f * d * d;
        } else if (lane == 3) {   // h
            float hp = __expf(q0) * ah * invW;
            float t = __logf(t0 * (416.f / ah));
            float d = t - hp;
            l = scale * 0.5f * d * d;
        } else {                  // cls channels 5..32
            l = bce01(t0, sigf(q0));
        }
        // group 1: channels 33..64 (cls)
        float t1 = __ldg(tb + lane + 33), q1 = __ldg(pb + lane + 33);
        l += bce01(t1, sigf(q1));
        // group 2: channels 65..84 (cls)
        if (lane < 20) {
            float t2 = __ldg(tb + lane + 65), q2 = __ldg(pb + lane + 65);
            l += bce01(t2, sigf(q2));
        }
        acc += l;
    }
    #pragma unroll
    for (int o = 16; o; o >>= 1) acc += __shfl_xor_sync(FULL, acc, o);
    if (lane == 0 && acc != 0.f) atomicAdd(out + b, acc);
}

// ---- k_main -------------------------------------------------------------------
__global__ __launch_bounds__(256)
void k_main(const float* __restrict__ yt,
            const float* __restrict__ p13,
            const float* __restrict__ p26,
            const float* __restrict__ p52,
            float* __restrict__ out) {
    if (blockIdx.x < NPOS) {
        pos_work(blockIdx.x, yt, p13, p26, p52, out);
        return;
    }
    __shared__ float s_lo[8], s_hi[8];

    int base = (blockIdx.x - NPOS) * 512;
    int eA = base + threadIdx.x;
    int eB = eA + 256;

    AnchGeom gA = anchor_setup(eA, p13, p26, p52);
    AnchGeom gB = anchor_setup(eB, p13, p26, p52);

    float ignA, ignB;
    box_scan(gA, gB, gA.bl == gB.bl, ignA, ignB);

    float lA = gA.confbce * ((gA.obj > 0.f) ? 1.f : ignA);
    float lB = gB.confbce * ((gB.obj > 0.f) ? 1.f : ignB);

    // block spans at most 2 batch indices
    int b_lo = base / TOT;
    int bound = (b_lo + 1) * TOT;
    float accLo = ((eA < bound) ? lA : 0.f) + ((eB < bound) ? lB : 0.f);
    float accHi = ((eA >= bound) ? lA : 0.f) + ((eB >= bound) ? lB : 0.f);

    const unsigned FULL = 0xffffffffu;
    #pragma unroll
    for (int o = 16; o; o >>= 1) {
        accLo += __shfl_xor_sync(FULL, accLo, o);
        accHi += __shfl_xor_sync(FULL, accHi, o);
    }
    int wid = threadIdx.x >> 5, lane = threadIdx.x & 31;
    if (lane == 0) { s_lo[wid] = accLo; s_hi[wid] = accHi; }
    __syncthreads();
    if (wid == 0) {
        float vl = (lane < 8) ? s_lo[lane] : 0.f;
        float vh = (lane < 8) ? s_hi[lane] : 0.f;
        #pragma unroll
        for (int o = 4; o; o >>= 1) {
            vl += __shfl_xor_sync(FULL, vl, o);
            vh += __shfl_xor_sync(FULL, vh, o);
        }
        if (lane == 0) {
            atomicAdd(out + b_lo, vl);
            int b_hi = b_lo + 1;
            if (b_hi < NB && vh != 0.f) atomicAdd(out + b_hi, vh);
        }
    }
}

// ---------------------------------------------------------------------------
extern "C" void kernel_launch(void* const* d_in, const int* in_sizes, int n_in,
                              void* d_out, int out_size) {
    const float* yt  = (const float*)d_in[0];
    const float* p13 = (const float*)d_in[1];
    const float* p26 = (const float*)d_in[2];
    const float* p52 = (const float*)d_in[3];
    float* out = (float*)d_out;

    k_init<<<1, 128>>>(out);
    k_collect<<<NMAIN, 256>>>(yt);
    k_main<<<NMAIN + NPOS, 256>>>(yt, p13, p26, p52, out);
}